// round 1
// baseline (speedup 1.0000x reference)
#include <cuda_runtime.h>
#include <math.h>

// Problem constants
#define B_  4
#define T_  2048
#define D_  1024
#define H_  16
#define HD_ 64
#define F_  128
#define C_  64
#define N_  32            // T/C
#define BT_ (B_*T_)       // 8192
#define BHT_ (B_*H_*T_)   // 131072
#define NCHUNK_ (B_*H_*N_) // 2048

// ---------------- scratch (device globals; no allocations allowed) ----------
__device__ float g_x [BT_*D_];        // normalized x
__device__ float g_q [BT_*D_];        // q projection [BT, D]
__device__ float g_k [BT_*D_];        // k projection
__device__ float g_v [BT_*D_];        // v projection
__device__ float g_qf[BHT_*F_];       // hedgehog q features [b,h,t,f]
__device__ float g_kf[BHT_*F_];       // hedgehog k features
__device__ float g_kv[NCHUNK_*F_*HD_];// per-chunk kv states -> exclusive cumsum
__device__ float g_o [BT_*D_];        // attention output in [B,T,H*HD]

// ---------------- fused add + RMSNorm --------------------------------------
__global__ __launch_bounds__(256)
void addnorm_kernel(const float* __restrict__ hs, const float* __restrict__ res,
                    const float* __restrict__ w, float* __restrict__ resid_out,
                    float* __restrict__ x_out)
{
    __shared__ float red[8];
    const int row = blockIdx.x;
    const int t = threadIdx.x;
    const float4* h4 = (const float4*)(hs  + (size_t)row*D_);
    const float4* r4 = (const float4*)(res + (size_t)row*D_);
    float4*      ro4 = (float4*)(resid_out + (size_t)row*D_);
    float4*      xo4 = (float4*)(x_out     + (size_t)row*D_);

    float4 h = h4[t], r = r4[t];
    float4 s = make_float4(h.x+r.x, h.y+r.y, h.z+r.z, h.w+r.w);
    ro4[t] = s;
    float ss = s.x*s.x + s.y*s.y + s.z*s.z + s.w*s.w;
    #pragma unroll
    for (int o = 16; o; o >>= 1) ss += __shfl_xor_sync(0xffffffffu, ss, o);
    if ((t & 31) == 0) red[t >> 5] = ss;
    __syncthreads();
    float tot = 0.f;
    #pragma unroll
    for (int i = 0; i < 8; i++) tot += red[i];
    float rstd = rsqrtf(tot * (1.0f/1024.0f) + 1e-5f);
    float4 wv = ((const float4*)w)[t];
    xo4[t] = make_float4(s.x*rstd*wv.x, s.y*rstd*wv.y, s.z*rstd*wv.z, s.w*rstd*wv.w);
}

// ---------------- fp32 SGEMM: C[M,N] = A[M,K] @ B[K,N] ----------------------
// 128x128 block tile, BK=8, 256 threads, 8x8 per thread (split 4+4 over 64).
__global__ __launch_bounds__(256)
void sgemm128(const float* __restrict__ A, const float* __restrict__ B,
              float* __restrict__ C, int M, int N, int K)
{
    __shared__ float As[8][128];
    __shared__ float Bs[8][128];
    const int tid = threadIdx.x;
    const int bx = blockIdx.x, by = blockIdx.y;
    const int tx = tid & 15, ty = tid >> 4;

    const int aRow = tid >> 1;
    const int aCol = (tid & 1) * 4;
    const int bRow = tid >> 5;
    const int bCol = (tid & 31) * 4;

    const float* Ap = A + (size_t)(by*128 + aRow) * K + aCol;
    const float* Bp = B + (size_t)bRow * N + bx*128 + bCol;

    float acc[8][8];
    #pragma unroll
    for (int i = 0; i < 8; i++)
        #pragma unroll
        for (int j = 0; j < 8; j++) acc[i][j] = 0.f;

    for (int k0 = 0; k0 < K; k0 += 8) {
        float4 a = *(const float4*)(Ap + k0);
        As[aCol+0][aRow] = a.x; As[aCol+1][aRow] = a.y;
        As[aCol+2][aRow] = a.z; As[aCol+3][aRow] = a.w;
        float4 b = *(const float4*)(Bp + (size_t)k0 * N);
        *(float4*)&Bs[bRow][bCol] = b;
        __syncthreads();
        #pragma unroll
        for (int k = 0; k < 8; k++) {
            float4 a0 = *(const float4*)&As[k][ty*4];
            float4 a1 = *(const float4*)&As[k][ty*4 + 64];
            float4 b0 = *(const float4*)&Bs[k][tx*4];
            float4 b1 = *(const float4*)&Bs[k][tx*4 + 64];
            float ra[8] = {a0.x,a0.y,a0.z,a0.w, a1.x,a1.y,a1.z,a1.w};
            float rb[8] = {b0.x,b0.y,b0.z,b0.w, b1.x,b1.y,b1.z,b1.w};
            #pragma unroll
            for (int i = 0; i < 8; i++)
                #pragma unroll
                for (int j = 0; j < 8; j++)
                    acc[i][j] = fmaf(ra[i], rb[j], acc[i][j]);
        }
        __syncthreads();
    }
    #pragma unroll
    for (int ih = 0; ih < 2; ih++) {
        #pragma unroll
        for (int i = 0; i < 4; i++) {
            int row = by*128 + ih*64 + ty*4 + i;
            float* Cp = C + (size_t)row * N + bx*128;
            float4 v0 = make_float4(acc[ih*4+i][0], acc[ih*4+i][1],
                                    acc[ih*4+i][2], acc[ih*4+i][3]);
            float4 v1 = make_float4(acc[ih*4+i][4], acc[ih*4+i][5],
                                    acc[ih*4+i][6], acc[ih*4+i][7]);
            *(float4*)(Cp + tx*4)      = v0;
            *(float4*)(Cp + 64 + tx*4) = v1;
        }
    }
}

// ---------------- hedgehog feature map --------------------------------------
// y = W @ x + b (64x64), feat = softmax([y, -y]) * scale. One warp per token.
__global__ __launch_bounds__(256)
void hedgehog_kernel(const float* __restrict__ proj, const float* __restrict__ w,
                     const float* __restrict__ bias, float* __restrict__ feat,
                     float scale)
{
    __shared__ float ws[64*65];
    __shared__ float xs[8][64];
    __shared__ float bs[64];
    const int tid = threadIdx.x;
    for (int i = tid; i < 4096; i += 256) { int e = i >> 6, d = i & 63; ws[e*65+d] = w[i]; }
    if (tid < 64) bs[tid] = bias[tid];
    const int warp = tid >> 5, lane = tid & 31;
    const int g = blockIdx.x*8 + warp;          // (b*H+h)*T + t
    const int b = g >> 15;
    const int h = (g >> 11) & 15;
    const int t = g & 2047;
    const float* xp = proj + ((size_t)(b*T_ + t))*D_ + h*HD_;
    xs[warp][lane]      = xp[lane];
    xs[warp][lane + 32] = xp[lane + 32];
    __syncthreads();

    float y0 = bs[lane], y1 = bs[lane+32];
    const float* w0 = &ws[lane*65];
    const float* w1 = &ws[(lane+32)*65];
    #pragma unroll
    for (int d = 0; d < 64; d++) {
        float xv = xs[warp][d];
        y0 = fmaf(w0[d], xv, y0);
        y1 = fmaf(w1[d], xv, y1);
    }
    float m = fmaxf(fabsf(y0), fabsf(y1));
    #pragma unroll
    for (int o = 16; o; o >>= 1) m = fmaxf(m, __shfl_xor_sync(0xffffffffu, m, o));
    float e0 = __expf(y0 - m), e1 = __expf(y1 - m);
    float e2 = __expf(-y0 - m), e3 = __expf(-y1 - m);
    float z = e0 + e1 + e2 + e3;
    #pragma unroll
    for (int o = 16; o; o >>= 1) z += __shfl_xor_sync(0xffffffffu, z, o);
    float inv = scale / z;
    float* fp = feat + (size_t)g * F_;
    fp[lane]      = e0 * inv;
    fp[lane + 32] = e1 * inv;
    fp[lane + 64] = e2 * inv;
    fp[lane + 96] = e3 * inv;
}

// ---------------- phase A: per-chunk kv[f,d] = sum_c k[c,f] v[c,d] ----------
__global__ __launch_bounds__(256)
void chunk_kv_kernel(const float* __restrict__ kfeat, const float* __restrict__ vproj,
                     float* __restrict__ kv)
{
    __shared__ float ks[64][128];
    __shared__ float vs[64][68];
    const int blk = blockIdx.x;          // bh*N + n
    const int n = blk & 31, bh = blk >> 5;
    const int b = bh >> 4, h = bh & 15;
    const int tid = threadIdx.x;
    const float* kp = kfeat + ((size_t)bh*T_ + n*C_)*F_;
    for (int i = tid; i < 64*128; i += 256) ks[i>>7][i&127] = kp[i];
    const float* vp = vproj + ((size_t)(b*T_ + n*C_))*D_ + h*HD_;
    for (int i = tid; i < 64*64; i += 256) vs[i>>6][i&63] = vp[(i>>6)*D_ + (i&63)];
    __syncthreads();
    const int tx = tid & 15, ty = tid >> 4;
    float acc[8][4] = {};
    for (int c = 0; c < 64; c++) {
        float kr[8], vr[4];
        #pragma unroll
        for (int i = 0; i < 8; i++) kr[i] = ks[c][ty*8+i];
        #pragma unroll
        for (int j = 0; j < 4; j++) vr[j] = vs[c][tx*4+j];
        #pragma unroll
        for (int i = 0; i < 8; i++)
            #pragma unroll
            for (int j = 0; j < 4; j++)
                acc[i][j] = fmaf(kr[i], vr[j], acc[i][j]);
    }
    float* out = kv + (size_t)blk * (F_*HD_);
    #pragma unroll
    for (int i = 0; i < 8; i++) {
        float4 v = make_float4(acc[i][0], acc[i][1], acc[i][2], acc[i][3]);
        *(float4*)&out[(ty*8+i)*64 + tx*4] = v;
    }
}

// ---------------- phase B: exclusive cumsum over chunks (in place) ----------
__global__ __launch_bounds__(1024)
void kv_scan_kernel(float* __restrict__ kv)
{
    const int blk = blockIdx.x;          // 512 blocks: bh = blk>>3, seg = blk&7
    const int bh = blk >> 3, seg = blk & 7;
    const int e = seg*1024 + threadIdx.x;
    size_t base = (size_t)bh * N_ * (F_*HD_) + e;
    float acc = 0.f;
    for (int n = 0; n < N_; n++) {
        size_t idx = base + (size_t)n * (F_*HD_);
        float t = kv[idx];
        kv[idx] = acc;
        acc += t;
    }
}

// ---------------- phase C: out = q@S_excl + tril(q@k^T)@v -------------------
__global__ __launch_bounds__(256)
void chunk_out_kernel(const float* __restrict__ qfeat, const float* __restrict__ kfeat,
                      const float* __restrict__ vproj, const float* __restrict__ kv,
                      float* __restrict__ o_flat)
{
    extern __shared__ float sm[];
    float* qs = sm;                 // [64][129] = 8256
    float* kS = qs + 64*129;        // union: kc [64][129] then S [128][65]; size 8320
    float* vs = kS + 8320;          // [64][65] = 4160
    float* sc = vs + 64*65;         // [64][65] = 4160
    const int blk = blockIdx.x;
    const int n = blk & 31, bh = blk >> 5;
    const int b = bh >> 4, h = bh & 15;
    const int tid = threadIdx.x;
    const float* qp = qfeat + ((size_t)bh*T_ + n*C_)*F_;
    const float* kp = kfeat + ((size_t)bh*T_ + n*C_)*F_;
    for (int i = tid; i < 8192; i += 256) {
        int c = i >> 7, f = i & 127;
        qs[c*129 + f] = qp[i];
        kS[c*129 + f] = kp[i];
    }
    const float* vp = vproj + ((size_t)(b*T_ + n*C_))*D_ + h*HD_;
    for (int i = tid; i < 4096; i += 256) { int c = i>>6, d = i&63; vs[c*65+d] = vp[c*D_+d]; }
    __syncthreads();

    const int tx = tid & 15, ty = tid >> 4;
    // scores s[c,m] = sum_f q[c,f] k[m,f], masked to m <= c
    float a1[4][4] = {};
    for (int f = 0; f < 128; f++) {
        float qr[4], kr[4];
        #pragma unroll
        for (int i = 0; i < 4; i++) qr[i] = qs[(ty*4+i)*129 + f];
        #pragma unroll
        for (int j = 0; j < 4; j++) kr[j] = kS[(tx*4+j)*129 + f];
        #pragma unroll
        for (int i = 0; i < 4; i++)
            #pragma unroll
            for (int j = 0; j < 4; j++)
                a1[i][j] = fmaf(qr[i], kr[j], a1[i][j]);
    }
    #pragma unroll
    for (int i = 0; i < 4; i++)
        #pragma unroll
        for (int j = 0; j < 4; j++) {
            int c = ty*4+i, m = tx*4+j;
            sc[c*65 + m] = (m <= c) ? a1[i][j] : 0.f;
        }
    __syncthreads();
    // overwrite kc region with S_excl [F,HD]
    const float* Sp = kv + (size_t)blk * (F_*HD_);
    for (int i = tid; i < 8192; i += 256) { int f = i>>6, d = i&63; kS[f*65+d] = Sp[i]; }
    __syncthreads();

    float acc[4][4] = {};
    for (int f = 0; f < 128; f++) {       // inter: q @ S_excl
        float qr[4], sr[4];
        #pragma unroll
        for (int i = 0; i < 4; i++) qr[i] = qs[(ty*4+i)*129 + f];
        #pragma unroll
        for (int j = 0; j < 4; j++) sr[j] = kS[f*65 + tx*4 + j];
        #pragma unroll
        for (int i = 0; i < 4; i++)
            #pragma unroll
            for (int j = 0; j < 4; j++)
                acc[i][j] = fmaf(qr[i], sr[j], acc[i][j]);
    }
    for (int m = 0; m < 64; m++) {        // intra: scores @ v
        float scr[4], vr[4];
        #pragma unroll
        for (int i = 0; i < 4; i++) scr[i] = sc[(ty*4+i)*65 + m];
        #pragma unroll
        for (int j = 0; j < 4; j++) vr[j] = vs[m*65 + tx*4 + j];
        #pragma unroll
        for (int i = 0; i < 4; i++)
            #pragma unroll
            for (int j = 0; j < 4; j++)
                acc[i][j] = fmaf(scr[i], vr[j], acc[i][j]);
    }
    // write directly in [B, T, H*HD] layout (folds the transpose)
    float* op = o_flat + ((size_t)(b*T_ + n*C_))*D_ + h*HD_;
    #pragma unroll
    for (int i = 0; i < 4; i++) {
        int c = ty*4 + i;
        float4 v = make_float4(acc[i][0], acc[i][1], acc[i][2], acc[i][3]);
        *(float4*)&op[(size_t)c*D_ + tx*4] = v;
    }
}

// ---------------- launcher ---------------------------------------------------
extern "C" void kernel_launch(void* const* d_in, const int* in_sizes, int n_in,
                              void* d_out, int out_size)
{
    const float* hs   = (const float*)d_in[0];
    const float* res  = (const float*)d_in[1];
    const float* nw   = (const float*)d_in[2];
    const float* w_q  = (const float*)d_in[3];
    const float* w_k  = (const float*)d_in[4];
    const float* w_v  = (const float*)d_in[5];
    const float* w_o  = (const float*)d_in[6];
    const float* hqw  = (const float*)d_in[7];
    const float* hqb  = (const float*)d_in[8];
    const float* hkw  = (const float*)d_in[9];
    const float* hkb  = (const float*)d_in[10];
    float* out = (float*)d_out;              // [o (BT*D), resid (BT*D)]

    float *px, *pq, *pk, *pv, *pqf, *pkf, *pkv, *po;
    cudaGetSymbolAddress((void**)&px,  g_x);
    cudaGetSymbolAddress((void**)&pq,  g_q);
    cudaGetSymbolAddress((void**)&pk,  g_k);
    cudaGetSymbolAddress((void**)&pv,  g_v);
    cudaGetSymbolAddress((void**)&pqf, g_qf);
    cudaGetSymbolAddress((void**)&pkf, g_kf);
    cudaGetSymbolAddress((void**)&pkv, g_kv);
    cudaGetSymbolAddress((void**)&po,  g_o);

    const int smem_c = (64*129 + 8320 + 64*65 + 64*65) * 4;   // 99584 bytes
    cudaFuncSetAttribute(chunk_out_kernel,
                         cudaFuncAttributeMaxDynamicSharedMemorySize, smem_c);

    // 1) fused add + RMSNorm; resid -> second half of d_out
    addnorm_kernel<<<BT_, 256>>>(hs, res, nw, out + (size_t)BT_*D_, px);

    // 2) QKV projections
    dim3 ggrid(D_/128, BT_/128);
    sgemm128<<<ggrid, 256>>>(px, w_q, pq, BT_, D_, D_);
    sgemm128<<<ggrid, 256>>>(px, w_k, pk, BT_, D_, D_);
    sgemm128<<<ggrid, 256>>>(px, w_v, pv, BT_, D_, D_);

    // 3) hedgehog features (q gets the F^-0.5 scale)
    hedgehog_kernel<<<BHT_/8, 256>>>(pq, hqw, hqb, pqf, 0.08838834764831845f);
    hedgehog_kernel<<<BHT_/8, 256>>>(pk, hkw, hkb, pkf, 1.0f);

    // 4) chunked linear attention
    chunk_kv_kernel<<<NCHUNK_, 256>>>(pkf, pv, pkv);
    kv_scan_kernel<<<512, 1024>>>(pkv);
    chunk_out_kernel<<<NCHUNK_, 256, smem_c>>>(pqf, pkf, pv, pkv, po);

    // 5) output projection -> first half of d_out
    sgemm128<<<ggrid, 256>>>(po, w_o, out, BT_, D_, D_);
}